// round 11
// baseline (speedup 1.0000x reference)
#include <cuda_runtime.h>
#include <math.h>

// BayesRingRNN collapses exactly to a 2-scalar recurrence per batch:
// r_i(t) = u(t)*cos(phi_i) + v(t)*sin(phi_i)   (rank-2 weights, r0 in span).
//
// One batch per 64-thread CTA (grid = B = 1024, ~7 CTAs/SM, <=7% imbalance).
//   warp 1: serial (u,v) chain -> private 8-deep smem ring (32-step chunks)
//   warp 0: expansion to (B,T,N), purely linear STG.128 addresses
// Pairing is 1:1 and fully decoupled: NO bar.sync, NO threadfence -- just
// st.release.cta / ld.acquire.cta on two monotone smem counters. Producer is
// the HIGHER wid (SMSP arbiter is hi-wid-first -> polling can't starve it).

#define NN 80
#define TT 1500
#define CH 32
#define NCHUNK ((TT + CH - 1) / CH)   // 47 (last chunk = 28 steps)
#define NBUF 8

__device__ __forceinline__ void sts_release(int* sptr, int v) {
    unsigned a = (unsigned)__cvta_generic_to_shared(sptr);
    asm volatile("st.release.cta.shared.b32 [%0], %1;" :: "r"(a), "r"(v) : "memory");
}
__device__ __forceinline__ int lds_acquire(const int* sptr) {
    unsigned a = (unsigned)__cvta_generic_to_shared(sptr);
    int v;
    asm volatile("ld.acquire.cta.shared.b32 %0, [%1];" : "=r"(v) : "r"(a) : "memory");
    return v;
}

__global__ void __launch_bounds__(64, 7)
ring_kernel(const float* __restrict__ inputs,   // (B,T,2)
            const float* __restrict__ phi,      // (N,)
            float* __restrict__ out,            // (B,T,N) then (1,B,N)
            int B, float kz, long long out_size)
{
    __shared__ float4 c4s[NN / 4], s4s[NN / 4];
    __shared__ float2 ring[NBUF][CH];    // 2 KB private ring
    __shared__ int    prod_cnt;          // chunks produced (monotone)
    __shared__ int    cons_cnt;          // chunks consumed (monotone)

    const int tid  = threadIdx.x;
    const int wid  = tid >> 5;
    const int lane = tid & 31;
    const int b    = blockIdx.x;
    if (b >= B) return;

    for (int i = tid; i < NN; i += 64) {
        float s, c; sincosf(phi[i], &s, &c);
        reinterpret_cast<float*>(c4s)[i] = c;
        reinterpret_cast<float*>(s4s)[i] = s;
    }
    if (tid == 0) { prod_cnt = 0; cons_cnt = 0; }
    __syncthreads();

    if (wid == 1) {
        // --------------------------------------------------------- producer
        const float C1 = 0.01f / 3.0f;   // DT/(KP+KV)
        const float C3 = 2.0f / 3.0f;    // a_odd
        float u = 10.0f, v = 0.0f;       // r0 = 10*cos(phi) -> (10,0) exactly

        const float2* __restrict__ inp =
            reinterpret_cast<const float2*>(inputs) + (size_t)b * TT;
        float2 nx = inp[lane];           // prefetch chunk 0

        for (int c = 0; c < NCHUNK; ++c) {
            const int t = c * CH;
            const int len = (c == NCHUNK - 1) ? (TT - t) : CH;

            // ring backpressure (only this pair's consumer)
            if (c >= NBUF && lane == 0) {
                while (*(volatile int*)&cons_cnt < c - NBUF + 1) __nanosleep(200);
            }
            __syncwarp();

            const float2 x = nx;
            if (t + CH + lane < TT) nx = inp[t + CH + lane];

            float kc = 0.f, ks = 0.f, gi = 0.f;
            if (lane < len) {
                float s, co; sincosf(x.x, &s, &co);
                kc = kz * co; ks = kz * s; gi = C3 * x.y;
            }
            float su = u, sv = v;
            #pragma unroll 4
            for (int j = 0; j < len; ++j) {
                const float gij = __shfl_sync(0xffffffffu, gi, j);
                const float kcj = __shfl_sync(0xffffffffu, kc, j);
                const float ksj = __shfl_sync(0xffffffffu, ks, j);

                const float xx = fmaf(u, u, v * v);   // |z|^2 > 0 always
                const float y  = rsqrtf(xx);          // MUFU.RSQ
                const float d  = fmaf(-(C1 * xx), y, 1.0f);
                const float nu = fmaf(d, u, fmaf(-gij, v, kcj));
                const float nv = fmaf(d, v, fmaf( gij, u, ksj));
                u = nu; v = nv;
                if (j == lane) { su = u; sv = v; }
            }
            if (lane < len) ring[c & (NBUF - 1)][lane] = make_float2(su, sv);
            __syncwarp();                             // warp-scope ordering
            if (lane == 0) sts_release(&prod_cnt, c + 1);
        }

        // r_final (1,B,N) after the (B,T,N) block
        const long long base = (long long)B * TT * NN;
        if (out_size >= base + (long long)B * NN && lane < NN / 4) {
            const float4 cc = c4s[lane], ss = s4s[lane];
            float4 o;
            o.x = fmaf(v, ss.x, u * cc.x);
            o.y = fmaf(v, ss.y, u * cc.y);
            o.z = fmaf(v, ss.z, u * cc.z);
            o.w = fmaf(v, ss.w, u * cc.w);
            reinterpret_cast<float4*>(out + base + (size_t)b * NN)[lane] = o;
        }
    } else {
        // -------------------------------------------------------- consumer
        float4* __restrict__ o4 =
            reinterpret_cast<float4*>(out) + (size_t)b * TT * (NN / 4);

        for (int c = 0; c < NCHUNK; ++c) {
            if (lane == 0) {
                while (lds_acquire(&prod_cnt) < c + 1) __nanosleep(100);
            }
            __syncwarp();                             // broadcast acquire

            const int t0    = c * CH;
            const int total = ((c == NCHUNK - 1) ? (TT - t0) : CH) * 20;
            const float2* __restrict__ uvb = ring[c & (NBUF - 1)];

            #pragma unroll 4
            for (int l = lane; l < total; l += 32) {
                const unsigned step = (unsigned)l / 20u;   // mul-shift
                const int n4 = l - (int)step * 20;
                const float2 z = uvb[step];                // LDS broadcast-ish
                const float4 cc = c4s[n4];
                const float4 ss = s4s[n4];
                float4 o;
                o.x = fmaf(z.y, ss.x, z.x * cc.x);
                o.y = fmaf(z.y, ss.y, z.x * cc.y);
                o.z = fmaf(z.y, ss.z, z.x * cc.z);
                o.w = fmaf(z.y, ss.w, z.x * cc.w);
                __stcs(&o4[t0 * 20 + l], o);               // linear 512B/warp-instr
            }
            __syncwarp();                                  // uv reads done
            if (lane == 0) *(volatile int*)&cons_cnt = c + 1;
        }
    }
}

// --- host-side exact replica of the reference's _xi_inv (double precision) --
static double xi_f(double a, double target)
{
    const double x = (a / 2.0) * (a / 2.0);
    double t0 = 1.0, t1 = a / 2.0;
    double i0 = t0, i1 = t1;
    for (int k = 1; k < 30; ++k) {
        t0 *= x / ((double)k * (double)k);
        t1 *= x / ((double)k * (double)(k + 1));
        i0 += t0;
        i1 += t1;
    }
    return a * i1 / i0 - target;
}

static float compute_kappa_z()
{
    const double target = 15.0 * 0.01;
    double lo = 1e-3, hi = 50.0;
    for (int i = 0; i < 200; ++i) {
        const double mid = 0.5 * (lo + hi);
        if (xi_f(lo, target) * xi_f(mid, target) <= 0.0) hi = mid;
        else lo = mid;
    }
    return (float)(0.5 * (lo + hi));
}

extern "C" void kernel_launch(void* const* d_in, const int* in_sizes, int n_in,
                              void* d_out, int out_size)
{
    const float* inputs = (const float*)d_in[0];  // (B,T,2)
    const float* phi    = (const float*)d_in[4];  // (N,)
    float* out = (float*)d_out;

    const int B = in_sizes[0] / (2 * TT);
    const float kz = compute_kappa_z();

    ring_kernel<<<B, 64>>>(inputs, phi, out, B, kz, (long long)out_size);
}

// round 12
// speedup vs baseline: 3.9309x; 3.9309x over previous
#include <cuda_runtime.h>
#include <math.h>

// BayesRingRNN collapses exactly to a 2-scalar recurrence per batch:
// r_i(t) = u(t)*cos(phi_i) + v(t)*sin(phi_i)   (rank-2 weights, r0 in span).
//
// One warp per batch, ZERO synchronization. Software pipeline inside the
// warp: while computing the serial chain for chunk c (32 steps, rsqrt path,
// ~28 cyc/step latency-bound), the SAME loop stores chunk c-1 (lane j holds
// the step-j state from the previous chunk; 20 lanes emit one STG.128 per
// step). The store stream is independent of the live chain, so it fills the
// RSQ stall slots -> warp throughput is issue/HBM-bound, not latency-bound.

#define NN 80
#define TT 1500
#define CH 32
#define NFULL (TT / CH)        // 46 full chunks
#define REM   (TT - NFULL*CH)  // 28

__global__ void __launch_bounds__(128, 8)
ring_kernel(const float* __restrict__ inputs,   // (B,T,2)
            const float* __restrict__ phi,      // (N,)
            float* __restrict__ out,            // (B,T,N) then (1,B,N)
            int B, float kz, long long out_size)
{
    const int b    = (blockIdx.x * blockDim.x + threadIdx.x) >> 5;
    const int lane = threadIdx.x & 31;
    if (b >= B) return;

    // Per-lane output basis: lanes 0..19 own neurons 4l..4l+3
    float4 c4 = make_float4(0.f, 0.f, 0.f, 0.f);
    float4 s4 = make_float4(0.f, 0.f, 0.f, 0.f);
    if (lane < NN / 4) {
        sincosf(phi[4 * lane + 0], &s4.x, &c4.x);
        sincosf(phi[4 * lane + 1], &s4.y, &c4.y);
        sincosf(phi[4 * lane + 2], &s4.z, &c4.z);
        sincosf(phi[4 * lane + 3], &s4.w, &c4.w);
    }

    // KP=1, KV=2, DT=0.01: decay/drive terms cancel to  d = 1 - (DT/3)|z|
    const float C1 = 0.01f / 3.0f;   // DT/(KP+KV)
    const float C3 = 2.0f / 3.0f;    // a_odd

    float u = 10.0f, v = 0.0f;       // r0 = 10*cos(phi) -> (10,0) exactly
    float psu = 0.f, psv = 0.f;      // lane j: state after step j of prev chunk

    const float2* __restrict__ inp =
        reinterpret_cast<const float2*>(inputs) + (size_t)b * TT;
    float4* __restrict__ o4 =
        reinterpret_cast<float4*>(out) + (size_t)b * TT * (NN / 4);

    float2 nx = inp[lane];           // prefetch chunk 0

    // ---------------- chunk 0: compute only (nothing to store yet) --------
    {
        const float2 x = nx;
        nx = inp[CH + lane];
        float s, co; sincosf(x.x, &s, &co);
        const float kc = kz * co, ks = kz * s, gi = C3 * x.y;
        float su = u, sv = v;
        #pragma unroll 8
        for (int j = 0; j < CH; ++j) {
            const float gij = __shfl_sync(0xffffffffu, gi, j);
            const float kcj = __shfl_sync(0xffffffffu, kc, j);
            const float ksj = __shfl_sync(0xffffffffu, ks, j);
            const float xx = fmaf(u, u, v * v);
            const float y  = rsqrtf(xx);
            const float d  = fmaf(-(C1 * xx), y, 1.0f);
            const float nu = fmaf(d, u, fmaf(-gij, v, kcj));
            const float nv = fmaf(d, v, fmaf( gij, u, ksj));
            u = nu; v = nv;
            if (j == lane) { su = u; sv = v; }
        }
        psu = su; psv = sv;
    }

    // ---------------- chunks 1..45: fused compute(c) + store(c-1) ---------
    #pragma unroll 1
    for (int c = 1; c < NFULL; ++c) {
        const float2 x = nx;
        if ((c + 1) * CH + lane < TT) nx = inp[(c + 1) * CH + lane];

        float s, co; sincosf(x.x, &s, &co);
        const float kc = kz * co, ks = kz * s, gi = C3 * x.y;
        float su = u, sv = v;
        float4* __restrict__ ob = o4 + (size_t)(c - 1) * CH * (NN / 4) + lane;

        #pragma unroll 8
        for (int j = 0; j < CH; ++j) {
            // serial chain, chunk c
            const float gij = __shfl_sync(0xffffffffu, gi, j);
            const float kcj = __shfl_sync(0xffffffffu, kc, j);
            const float ksj = __shfl_sync(0xffffffffu, ks, j);
            const float xx = fmaf(u, u, v * v);
            const float y  = rsqrtf(xx);
            const float d  = fmaf(-(C1 * xx), y, 1.0f);
            const float nu = fmaf(d, u, fmaf(-gij, v, kcj));
            const float nv = fmaf(d, v, fmaf( gij, u, ksj));
            u = nu; v = nv;
            if (j == lane) { su = u; sv = v; }

            // independent store stream, chunk c-1 step j
            const float pu = __shfl_sync(0xffffffffu, psu, j);
            const float pv = __shfl_sync(0xffffffffu, psv, j);
            if (lane < NN / 4) {
                float4 o;
                o.x = fmaf(pv, s4.x, pu * c4.x);
                o.y = fmaf(pv, s4.y, pu * c4.y);
                o.z = fmaf(pv, s4.z, pu * c4.z);
                o.w = fmaf(pv, s4.w, pu * c4.w);
                __stcs(&ob[j * (NN / 4)], o);
            }
        }
        psu = su; psv = sv;
    }

    // ---------------- chunk 46 (28 steps) + store chunk 45 ----------------
    {
        const float2 x = nx;   // valid for lane < REM (guarded prefetch)
        float kc = 0.f, ks = 0.f, gi = 0.f;
        if (lane < REM) {
            float s, co; sincosf(x.x, &s, &co);
            kc = kz * co; ks = kz * s; gi = C3 * x.y;
        }
        float su = u, sv = v;
        float4* __restrict__ ob = o4 + (size_t)(NFULL - 1) * CH * (NN / 4) + lane;

        #pragma unroll 8
        for (int j = 0; j < CH; ++j) {
            if (j < REM) {
                const float gij = __shfl_sync(0xffffffffu, gi, j);
                const float kcj = __shfl_sync(0xffffffffu, kc, j);
                const float ksj = __shfl_sync(0xffffffffu, ks, j);
                const float xx = fmaf(u, u, v * v);
                const float y  = rsqrtf(xx);
                const float d  = fmaf(-(C1 * xx), y, 1.0f);
                const float nu = fmaf(d, u, fmaf(-gij, v, kcj));
                const float nv = fmaf(d, v, fmaf( gij, u, ksj));
                u = nu; v = nv;
                if (j == lane) { su = u; sv = v; }
            }
            const float pu = __shfl_sync(0xffffffffu, psu, j);
            const float pv = __shfl_sync(0xffffffffu, psv, j);
            if (lane < NN / 4) {
                float4 o;
                o.x = fmaf(pv, s4.x, pu * c4.x);
                o.y = fmaf(pv, s4.y, pu * c4.y);
                o.z = fmaf(pv, s4.z, pu * c4.z);
                o.w = fmaf(pv, s4.w, pu * c4.w);
                __stcs(&ob[j * (NN / 4)], o);
            }
        }
        psu = su; psv = sv;
    }

    // ---------------- epilogue: store chunk 46 (28 steps) -----------------
    {
        float4* __restrict__ ob = o4 + (size_t)NFULL * CH * (NN / 4) + lane;
        #pragma unroll 4
        for (int j = 0; j < REM; ++j) {
            const float pu = __shfl_sync(0xffffffffu, psu, j);
            const float pv = __shfl_sync(0xffffffffu, psv, j);
            if (lane < NN / 4) {
                float4 o;
                o.x = fmaf(pv, s4.x, pu * c4.x);
                o.y = fmaf(pv, s4.y, pu * c4.y);
                o.z = fmaf(pv, s4.z, pu * c4.z);
                o.w = fmaf(pv, s4.w, pu * c4.w);
                __stcs(&ob[j * (NN / 4)], o);
            }
        }
    }

    // r_final (1,B,N) appended after the (B,T,N) block
    const long long base = (long long)B * TT * NN;
    if (out_size >= base + (long long)B * NN && lane < NN / 4) {
        float4 o;
        o.x = fmaf(v, s4.x, u * c4.x);
        o.y = fmaf(v, s4.y, u * c4.y);
        o.z = fmaf(v, s4.z, u * c4.z);
        o.w = fmaf(v, s4.w, u * c4.w);
        reinterpret_cast<float4*>(out + base + (size_t)b * NN)[lane] = o;
    }
}

// --- host-side exact replica of the reference's _xi_inv (double precision) --
static double xi_f(double a, double target)
{
    const double x = (a / 2.0) * (a / 2.0);
    double t0 = 1.0, t1 = a / 2.0;
    double i0 = t0, i1 = t1;
    for (int k = 1; k < 30; ++k) {
        t0 *= x / ((double)k * (double)k);
        t1 *= x / ((double)k * (double)(k + 1));
        i0 += t0;
        i1 += t1;
    }
    return a * i1 / i0 - target;
}

static float compute_kappa_z()
{
    const double target = 15.0 * 0.01;
    double lo = 1e-3, hi = 50.0;
    for (int i = 0; i < 200; ++i) {
        const double mid = 0.5 * (lo + hi);
        if (xi_f(lo, target) * xi_f(mid, target) <= 0.0) hi = mid;
        else lo = mid;
    }
    return (float)(0.5 * (lo + hi));
}

extern "C" void kernel_launch(void* const* d_in, const int* in_sizes, int n_in,
                              void* d_out, int out_size)
{
    const float* inputs = (const float*)d_in[0];  // (B,T,2)
    const float* phi    = (const float*)d_in[4];  // (N,)
    float* out = (float*)d_out;

    const int B = in_sizes[0] / (2 * TT);
    const float kz = compute_kappa_z();

    const int threads = 128;                    // 4 warps = 4 batches per block
    const int blocks = (B * 32 + threads - 1) / threads;
    ring_kernel<<<blocks, threads>>>(inputs, phi, out, B, kz, (long long)out_size);
}